// round 13
// baseline (speedup 1.0000x reference)
#include <cuda_runtime.h>
#include <math.h>

// ---------------- problem constants -----------------------------------------
#define R_ROIS 2000
#define NOBJ   21
#define HFE    38
#define WFE    50
#define D1     25088        // 512*7*7
#define DH     4096
#define DH4    (DH/4)
#define NACT   27
#define HUMAN_LBL 14

#define SPLIT1 256
#define ROWS1  (D1/SPLIT1)  // 98
#define SPLIT2 256
#define ROWS2  (DH/SPLIT2)  // 16
#define SELC   8            // roi chunks in select stage A
#define HB     256          // hred blocks

// ---------------- device scratch --------------------------------------------
__device__ float  g_selv[20][SELC];
__device__ int    g_seli[20][SELC];
__device__ float  g_kept[20][4];
__device__ float  g_hbox[4];
__device__ float4 g_part1[SPLIT1 * DH4];
__device__ float4 g_part2[SPLIT2 * DH4];
__device__ float  g_hp[HB * 31];     // per-block head partials
__device__ float  g_sink[16];        // prefetch DCE guard

// ---------------------------------------------------------------------------
// Kernel 1a: select stage A — per-(label, roi-chunk) partial argmax of
// softmax prob (NMS_T=0 => greedy NMS keeps only the top-1 box per class).
// grid (SELC, 21): by<20 = labels; by==20 = Wloc/Wact L2 prefetch row.
// ---------------------------------------------------------------------------
__global__ void k_selA(const float* __restrict__ scores,
                       const float* __restrict__ Wloc,
                       const float* __restrict__ Wact)
{
    cudaGridDependencySynchronize();
    const int t = threadIdx.x;

    if (blockIdx.y == 20) {
        const float4* wl = (const float4*)Wloc;   // 4096 float4
        const float4* wa = (const float4*)Wact;   // 27648 float4
        float acc = 0.0f;
        for (int i = blockIdx.x * 256 + t; i < 4096;  i += SELC * 256) {
            const float4 v = __ldg(&wl[i]); acc += v.x + v.y + v.z + v.w;
        }
        for (int i = blockIdx.x * 256 + t; i < 27648; i += SELC * 256) {
            const float4 v = __ldg(&wa[i]); acc += v.x + v.y + v.z + v.w;
        }
        if (acc == 1e30f) g_sink[blockIdx.x] = acc;  // never true; defeats DCE
        return;
    }

    const int l   = blockIdx.y;
    const int cls = l + 1;
    const int r   = blockIdx.x * 256 + t;

    float best  = -1e30f;
    int   bestr = 0x7fffffff;
    if (r < R_ROIS) {
        const float* s = scores + r * NOBJ;
        float mx = s[0];
        #pragma unroll
        for (int j = 1; j < NOBJ; j++) mx = fmaxf(mx, s[j]);
        float sum = 0.0f;
        #pragma unroll
        for (int j = 0; j < NOBJ; j++) sum += expf(s[j] - mx);
        best  = s[cls] - (mx + logf(sum));
        bestr = r;
    }

    __shared__ float sb[256];
    __shared__ int   si[256];
    sb[t] = best; si[t] = bestr;
    __syncthreads();
    for (int st = 128; st > 0; st >>= 1) {
        if (t < st) {
            float ob = sb[t + st]; int oi = si[t + st];
            if (ob > sb[t] || (ob == sb[t] && oi < si[t])) { sb[t] = ob; si[t] = oi; }
        }
        __syncthreads();
    }
    if (t == 0) { g_selv[l][blockIdx.x] = sb[0]; g_seli[l][blockIdx.x] = si[0]; }
}

// ---------------------------------------------------------------------------
// Kernel 1b: select stage B — final argmax across chunks + box decode.
// ---------------------------------------------------------------------------
__global__ void k_selB(const float* __restrict__ off,
                       const float* __restrict__ rois,
                       const int*   __restrict__ imgshape)
{
    cudaGridDependencySynchronize();
    const int l = threadIdx.x;
    if (l >= 20) return;
    const int cls = l + 1;

    float best = -1e30f;
    int   r    = 0x7fffffff;
    #pragma unroll
    for (int c = 0; c < SELC; c++) {        // ascending chunks + strict >
        const float v = g_selv[l][c];       // == global first-max semantics
        if (v > best) { best = v; r = g_seli[l][c]; }
    }

    const float img0 = (float)imgshape[0];
    const float img1 = (float)imgshape[1];
    const float sy = (float)HFE / img0;
    const float sx = (float)WFE / img1;
    const float y1 = rois[r * 4 + 0] * sy;
    const float x1 = rois[r * 4 + 1] * sx;
    const float y2 = rois[r * 4 + 2] * sy;
    const float x2 = rois[r * 4 + 3] * sx;
    const float dy = off[r * (NOBJ * 4) + cls * 4 + 0] * 0.1f;
    const float dx = off[r * (NOBJ * 4) + cls * 4 + 1] * 0.1f;
    const float dh = off[r * (NOBJ * 4) + cls * 4 + 2] * 0.2f;
    const float dw = off[r * (NOBJ * 4) + cls * 4 + 3] * 0.2f;
    const float h  = y2 - y1, w = x2 - x1;
    const float cy = y1 + 0.5f * h, cx = x1 + 0.5f * w;
    const float cy2 = dy * h + cy, cx2 = dx * w + cx;
    const float h2 = expf(dh) * h, w2 = expf(dw) * w;
    float by1 = fminf(fmaxf(cy2 - 0.5f * h2, 0.0f), (float)HFE);
    float bx1 = fminf(fmaxf(cx2 - 0.5f * w2, 0.0f), (float)WFE);
    float by2 = fminf(fmaxf(cy2 + 0.5f * h2, 0.0f), (float)HFE);
    float bx2 = fminf(fmaxf(cx2 + 0.5f * w2, 0.0f), (float)WFE);
    g_kept[l][0] = by1; g_kept[l][1] = bx1;
    g_kept[l][2] = by2; g_kept[l][3] = bx2;
    if (l == HUMAN_LBL) {
        g_hbox[0] = by1; g_hbox[1] = bx1;
        g_hbox[2] = by2; g_hbox[3] = bx2;
    }
}

// ---------------------------------------------------------------------------
// roipool for one output element (same math as reference)
// ---------------------------------------------------------------------------
__device__ __forceinline__ float roipool_one(const float* __restrict__ x, int idx)
{
    const int c  = idx / 49;
    const int ph = (idx % 49) / 7;
    const int pw = idx % 7;

    const float y1 = g_hbox[0], x1 = g_hbox[1], y2 = g_hbox[2], x2 = g_hbox[3];
    const int xmin = (int)rintf(x1 * 0.0625f);
    const int ymin = (int)rintf(y1 * 0.0625f);
    const int xmax = (int)rintf(x2 * 0.0625f);
    const int ymax = (int)rintf(y2 * 0.0625f);
    const float rw = (float)max(xmax - xmin + 1, 1);
    const float rh = (float)max(ymax - ymin + 1, 1);

    int hs = ymin + (int)floorf((float)ph * rh / 7.0f);
    int he = ymin + (int)ceilf((float)(ph + 1) * rh / 7.0f);
    int ws = xmin + (int)floorf((float)pw * rw / 7.0f);
    int we = xmin + (int)ceilf((float)(pw + 1) * rw / 7.0f);
    hs = min(max(hs, 0), HFE); he = min(max(he, 0), HFE);
    ws = min(max(ws, 0), WFE); we = min(max(we, 0), WFE);

    float m = -1e30f;
    for (int yy = hs; yy < he; yy++)
        for (int xx = ws; xx < we; xx++)
            m = fmaxf(m, x[c * (HFE * WFE) + yy * WFE + xx]);
    return (hs < he && ws < we) ? ((m <= -0.5e30f) ? 0.0f : m) : 0.0f;
}

// ---------------------------------------------------------------------------
// Kernel 2: GEMV1 split-K with fused roipool prologue.
// grid (8, 256) = 2048 blocks, 128 threads. W1 streamed evict-first.
// ---------------------------------------------------------------------------
__global__ void k_gemv1(const float4* __restrict__ W1,
                        const float*  __restrict__ x)
{
    cudaGridDependencySynchronize();

    const int t  = threadIdx.x;
    const int i0 = blockIdx.y * ROWS1;

    __shared__ float sf[ROWS1];
    if (t < ROWS1) sf[t] = roipool_one(x, i0 + t);
    __syncthreads();

    const int j4 = blockIdx.x * 128 + t;
    float4 acc = make_float4(0.f, 0.f, 0.f, 0.f);
    const float4* __restrict__ w = W1 + (size_t)i0 * DH4 + j4;
    #pragma unroll 7
    for (int i = 0; i < ROWS1; i++) {
        const float4 v = __ldcs(&w[(size_t)i * DH4]);
        const float  s = sf[i];
        acc.x += s * v.x; acc.y += s * v.y;
        acc.z += s * v.z; acc.w += s * v.w;
    }
    g_part1[blockIdx.y * DH4 + j4] = acc;
}

// ---------------------------------------------------------------------------
// Kernel 3: GEMV2 with fused reduce1 prologue + ReLU zero-skip.
// grid (8, 256) = 2048 blocks, 128 threads.
// Prologue: rebuild this block's 16 h1 values from part1 (L2-hot, 64B-
// contiguous chunks; thread (jj=t&15,kq=t>>4) sums 32 partials, 8-way tree).
// Main: W2 row-skip on h1==0 (exact; ~50% of h1 is 0 from ReLU).
// ---------------------------------------------------------------------------
__global__ void k_gemv2(const float4* __restrict__ W2,
                        const float*  __restrict__ b1)
{
    cudaGridDependencySynchronize();   // part1 complete (gemv1 done)

    const int t  = threadIdx.x;
    const int i0 = blockIdx.y * ROWS2;
    const float* p1 = (const float*)g_part1;

    __shared__ float sm[8][16];
    __shared__ float sf[ROWS2];
    {
        const int jj = t & 15;
        const int kq = t >> 4;             // 0..7
        float s = 0.0f;
        #pragma unroll 8
        for (int k = 0; k < SPLIT1 / 8; k++)
            s += p1[(size_t)(kq * (SPLIT1 / 8) + k) * DH + i0 + jj];
        sm[kq][jj] = s;
    }
    __syncthreads();
    if (t < ROWS2) {
        float s = b1[i0 + t];
        #pragma unroll
        for (int q = 0; q < 8; q++) s += sm[q][t];
        sf[t] = fmaxf(s, 0.0f);
    }
    __syncthreads();

    const int j4 = blockIdx.x * 128 + t;
    float4 acc = make_float4(0.f, 0.f, 0.f, 0.f);
    const float4* __restrict__ w = W2 + (size_t)i0 * DH4 + j4;
    #pragma unroll
    for (int i = 0; i < ROWS2; i++) {
        const float s = sf[i];
        if (s != 0.0f) {                   // block-uniform branch
            const float4 v = __ldcs(&w[(size_t)i * DH4]);
            acc.x += s * v.x; acc.y += s * v.y;
            acc.z += s * v.z; acc.w += s * v.w;
        }
    }
    g_part2[blockIdx.y * DH4 + j4] = acc;
}

// ---------------------------------------------------------------------------
// Kernel 4: fused reduce2 + heads partials. 256 blocks x 256 threads.
// Phase 1: block-spread rebuild of a 16-entry fc7 slice (4 float4 columns).
// Phase 2: 31 partial dot products against the (L2-prefetched) head weights.
// ---------------------------------------------------------------------------
__global__ void k_hred(const float4* __restrict__ b2,
                       const float* __restrict__ Wloc,
                       const float* __restrict__ Wact)
{
    cudaGridDependencySynchronize();

    const int t  = threadIdx.x;
    const int j0 = blockIdx.x * 16;          // first fc7 index of this block

    __shared__ float4 sm4[64][4];
    __shared__ float  fc7s[16];

    {   // phase 1: thread (jl4 = t&3, kq = t>>2) sums 4 float4 partials
        const int jl4 = t & 3;
        const int kq  = t >> 2;
        const int j4  = blockIdx.x * 4 + jl4;
        float4 a = make_float4(0.f, 0.f, 0.f, 0.f);
        #pragma unroll
        for (int k = 0; k < SPLIT2 / 64; k++) {
            const float4 v = g_part2[(size_t)(kq * (SPLIT2 / 64) + k) * DH4 + j4];
            a.x += v.x; a.y += v.y; a.z += v.z; a.w += v.w;
        }
        sm4[kq][jl4] = a;
    }
    __syncthreads();
    {
        const int jl4 = t & 3;
        const int kq  = t >> 2;
        for (int st = 32; st >= 1; st >>= 1) {
            if (kq < st) {
                const float4 v = sm4[kq + st][jl4];
                sm4[kq][jl4].x += v.x; sm4[kq][jl4].y += v.y;
                sm4[kq][jl4].z += v.z; sm4[kq][jl4].w += v.w;
            }
            __syncthreads();
        }
    }
    if (t < 4) {
        const int j4 = blockIdx.x * 4 + t;
        float4 s = b2[j4];
        const float4 v = sm4[0][t];
        fc7s[t * 4 + 0] = fmaxf(s.x + v.x, 0.f);
        fc7s[t * 4 + 1] = fmaxf(s.y + v.y, 0.f);
        fc7s[t * 4 + 2] = fmaxf(s.z + v.z, 0.f);
        fc7s[t * 4 + 3] = fmaxf(s.w + v.w, 0.f);
    }
    __syncthreads();

    // phase 2: partial dots. thread t -> (o = t/8, q = t%8), 2 terms each.
    __shared__ float sp[31][8];
    const int o = t >> 3;
    const int q = t & 7;
    if (o < 31) {
        float p = 0.0f;
        #pragma unroll
        for (int m = 0; m < 2; m++) {
            const int idx = q * 2 + m;
            const float f = fc7s[idx];
            p += (o < 4) ? f * Wloc[(j0 + idx) * 4 + o]
                         : f * Wact[(j0 + idx) * NACT + (o - 4)];
        }
        sp[o][q] = p;
    }
    __syncthreads();
    if (o < 31 && q == 0) {
        float s = 0.0f;
        #pragma unroll
        for (int m = 0; m < 8; m++) s += sp[o][m];
        g_hp[blockIdx.x * 31 + o] = s;
    }
}

// ---------------------------------------------------------------------------
// Kernel 5: final — sum head partials (2-stage), gaussian pick, assemble.
// 1 block, 256 threads: (o = t&31, chunk = t>>5) covers 31 outputs x 8 chunks.
// ---------------------------------------------------------------------------
__global__ void k_final(const float* __restrict__ bloc,
                        const float* __restrict__ bact,
                        const int*   __restrict__ imgshape,
                        float* __restrict__ out)
{
    cudaGridDependencySynchronize();

    const int t = threadIdx.x;
    const int o = t & 31;
    const int c = t >> 5;                    // 0..7
    __shared__ float sp2[8][32];
    __shared__ float locs[4];

    {
        float s = 0.0f;
        if (o < 31) {
            #pragma unroll 4
            for (int b = c * (HB / 8); b < (c + 1) * (HB / 8); b++)
                s += g_hp[b * 31 + o];
        }
        sp2[c][o] = s;
    }
    __syncthreads();
    if (t < 31) {
        float s = (t < 4) ? bloc[t] : bact[t - 4];
        #pragma unroll
        for (int m = 0; m < 8; m++) s += sp2[m][t];
        if (t < 4) locs[t] = s;
        else       out[8 + (t - 4)] = s;     // action scores
    }
    __syncthreads();
    if (t != 0) return;

    const float img0 = (float)imgshape[0];
    const float img1 = (float)imgshape[1];

    const float hb0 = g_hbox[0], hb1 = g_hbox[1], hb2 = g_hbox[2], hb3 = g_hbox[3];
    const float hw_ = hb3 - hb1, hh_ = hb2 - hb0;
    const float h4x = 0.5f * hw_, h4y = 0.5f * hh_;
    const float hw = fmaxf(hw_, 1e-3f), hh = fmaxf(hh_, 1e-3f);

    const float mw = locs[3] - locs[1], mh = locs[2] - locs[0];
    const float mu0 = 0.5f * mw, mu1 = 0.5f * mh, mu2 = mw, mu3 = mh;

    float best = -1.0f;
    int   bl   = 0;
    for (int l = 0; l < 20; l++) {
        if (l == HUMAN_LBL) continue;
        const float b0 = g_kept[l][0], b1 = g_kept[l][1];
        const float b2 = g_kept[l][2], b3 = g_kept[l][3];
        const float cw_ = b3 - b1, ch_ = b2 - b0;
        const float cx = 0.5f * cw_, cy = 0.5f * ch_;
        const float cw = fmaxf(cw_, 1e-3f), ch = fmaxf(ch_, 1e-3f);
        const float d0 = (cx - h4x) / hw - mu0;
        const float d1 = (cy - h4y) / hh - mu1;
        const float d2 = logf(cw / hw) - mu2;
        const float d3 = logf(ch / hh) - mu3;
        const float gau = expf(-(d0*d0 + d1*d1 + d2*d2 + d3*d3) /
                               (2.0f * 0.3f * 0.3f));
        if (gau > best) { best = gau; bl = l; }
    }

    const float invy = img0 / (float)HFE;
    const float invx = img1 / (float)WFE;
    out[0] = hb0 * invy; out[1] = hb1 * invx;
    out[2] = hb2 * invy; out[3] = hb3 * invx;
    out[4] = g_kept[bl][0] * invy; out[5] = g_kept[bl][1] * invx;
    out[6] = g_kept[bl][2] * invy; out[7] = g_kept[bl][3] * invx;
    out[35] = (float)HFE / img0;
}

// ---------------------------------------------------------------------------
// PDL launch helper
// ---------------------------------------------------------------------------
static void launch_pdl(const void* func, dim3 grid, dim3 block, void** args)
{
    cudaLaunchConfig_t cfg = {};
    cfg.gridDim  = grid;
    cfg.blockDim = block;
    cudaLaunchAttribute attr[1];
    attr[0].id = cudaLaunchAttributeProgrammaticStreamSerialization;
    attr[0].val.programmaticStreamSerializationAllowed = 1;
    cfg.attrs = attr;
    cfg.numAttrs = 1;
    cudaLaunchKernelExC(&cfg, func, args);
}

// ---------------------------------------------------------------------------
extern "C" void kernel_launch(void* const* d_in, const int* in_sizes, int n_in,
                              void* d_out, int out_size)
{
    const float* x        = (const float*)d_in[0];
    const float* pscores  = (const float*)d_in[1];
    const float* poff     = (const float*)d_in[2];
    const float* rois     = (const float*)d_in[3];
    const int*   imgshape = (const int*)  d_in[4];
    const float* W1f      = (const float*)d_in[5];
    const float* b1       = (const float*)d_in[6];
    const float* W2f      = (const float*)d_in[7];
    const float* b2f      = (const float*)d_in[8];
    const float* Wloc     = (const float*)d_in[9];
    const float* bloc     = (const float*)d_in[10];
    const float* Wact     = (const float*)d_in[11];
    const float* bact     = (const float*)d_in[12];
    float* out = (float*)d_out;
    const float4* W1 = (const float4*)W1f;
    const float4* W2 = (const float4*)W2f;
    const float4* b2 = (const float4*)b2f;

    {   void* a[] = {(void*)&pscores, (void*)&Wloc, (void*)&Wact};
        launch_pdl((const void*)k_selA, dim3(SELC, 21), dim3(256), a); }
    {   void* a[] = {(void*)&poff, (void*)&rois, (void*)&imgshape};
        launch_pdl((const void*)k_selB, dim3(1), dim3(32), a); }
    {   void* a[] = {(void*)&W1, (void*)&x};
        launch_pdl((const void*)k_gemv1, dim3(8, SPLIT1), dim3(128), a); }
    {   void* a[] = {(void*)&W2, (void*)&b1};
        launch_pdl((const void*)k_gemv2, dim3(8, SPLIT2), dim3(128), a); }
    {   void* a[] = {(void*)&b2, (void*)&Wloc, (void*)&Wact};
        launch_pdl((const void*)k_hred, dim3(HB), dim3(256), a); }
    {   void* a[] = {(void*)&bloc, (void*)&bact, (void*)&imgshape, (void*)&out};
        launch_pdl((const void*)k_final, dim3(1), dim3(256), a); }
}

// round 14
// speedup vs baseline: 1.0037x; 1.0037x over previous
#include <cuda_runtime.h>
#include <math.h>

// ---------------- problem constants -----------------------------------------
#define R_ROIS 2000
#define NOBJ   21
#define HFE    38
#define WFE    50
#define D1     25088        // 512*7*7
#define DH     4096
#define DH4    (DH/4)
#define NACT   27
#define HUMAN_LBL 14

#define SPLIT1 256
#define ROWS1  (D1/SPLIT1)  // 98
#define SPLIT2 256
#define ROWS2  (DH/SPLIT2)  // 16
#define SELC   8            // roi chunks in select stage A
#define HB     256          // hred blocks

// ---------------- device scratch --------------------------------------------
__device__ float  g_selv[20][SELC];
__device__ int    g_seli[20][SELC];
__device__ float  g_kept[20][4];
__device__ float  g_hbox[4];
__device__ float4 g_part1[SPLIT1 * DH4];
__device__ float4 g_h1f4[DH4];
__device__ float4 g_part2[SPLIT2 * DH4];
__device__ float  g_hp[HB * 31];     // per-block head partials
__device__ float  g_sink[16];        // prefetch DCE guard

// ---------------------------------------------------------------------------
// Kernel 1a: select stage A — per-(label, roi-chunk) partial argmax of
// softmax prob (NMS_T=0 => greedy NMS keeps only the top-1 box per class).
// grid (SELC, 21): by<20 = labels; by==20 = Wloc/Wact L2 prefetch row.
// ---------------------------------------------------------------------------
__global__ void k_selA(const float* __restrict__ scores,
                       const float* __restrict__ Wloc,
                       const float* __restrict__ Wact)
{
    cudaGridDependencySynchronize();
    const int t = threadIdx.x;

    if (blockIdx.y == 20) {
        const float4* wl = (const float4*)Wloc;   // 4096 float4
        const float4* wa = (const float4*)Wact;   // 27648 float4
        float acc = 0.0f;
        for (int i = blockIdx.x * 256 + t; i < 4096;  i += SELC * 256) {
            const float4 v = __ldg(&wl[i]); acc += v.x + v.y + v.z + v.w;
        }
        for (int i = blockIdx.x * 256 + t; i < 27648; i += SELC * 256) {
            const float4 v = __ldg(&wa[i]); acc += v.x + v.y + v.z + v.w;
        }
        if (acc == 1e30f) g_sink[blockIdx.x] = acc;  // never true; defeats DCE
        return;
    }

    const int l   = blockIdx.y;
    const int cls = l + 1;
    const int r   = blockIdx.x * 256 + t;

    float best  = -1e30f;
    int   bestr = 0x7fffffff;
    if (r < R_ROIS) {
        const float* s = scores + r * NOBJ;
        float mx = s[0];
        #pragma unroll
        for (int j = 1; j < NOBJ; j++) mx = fmaxf(mx, s[j]);
        float sum = 0.0f;
        #pragma unroll
        for (int j = 0; j < NOBJ; j++) sum += expf(s[j] - mx);
        best  = s[cls] - (mx + logf(sum));
        bestr = r;
    }

    __shared__ float sb[256];
    __shared__ int   si[256];
    sb[t] = best; si[t] = bestr;
    __syncthreads();
    for (int st = 128; st > 0; st >>= 1) {
        if (t < st) {
            float ob = sb[t + st]; int oi = si[t + st];
            if (ob > sb[t] || (ob == sb[t] && oi < si[t])) { sb[t] = ob; si[t] = oi; }
        }
        __syncthreads();
    }
    if (t == 0) { g_selv[l][blockIdx.x] = sb[0]; g_seli[l][blockIdx.x] = si[0]; }
}

// ---------------------------------------------------------------------------
// Kernel 1b: select stage B — final argmax across chunks + box decode.
// ---------------------------------------------------------------------------
__global__ void k_selB(const float* __restrict__ off,
                       const float* __restrict__ rois,
                       const int*   __restrict__ imgshape)
{
    cudaGridDependencySynchronize();
    const int l = threadIdx.x;
    if (l >= 20) return;
    const int cls = l + 1;

    float best = -1e30f;
    int   r    = 0x7fffffff;
    #pragma unroll
    for (int c = 0; c < SELC; c++) {        // ascending chunks + strict >
        const float v = g_selv[l][c];       // == global first-max semantics
        if (v > best) { best = v; r = g_seli[l][c]; }
    }

    const float img0 = (float)imgshape[0];
    const float img1 = (float)imgshape[1];
    const float sy = (float)HFE / img0;
    const float sx = (float)WFE / img1;
    const float y1 = rois[r * 4 + 0] * sy;
    const float x1 = rois[r * 4 + 1] * sx;
    const float y2 = rois[r * 4 + 2] * sy;
    const float x2 = rois[r * 4 + 3] * sx;
    const float dy = off[r * (NOBJ * 4) + cls * 4 + 0] * 0.1f;
    const float dx = off[r * (NOBJ * 4) + cls * 4 + 1] * 0.1f;
    const float dh = off[r * (NOBJ * 4) + cls * 4 + 2] * 0.2f;
    const float dw = off[r * (NOBJ * 4) + cls * 4 + 3] * 0.2f;
    const float h  = y2 - y1, w = x2 - x1;
    const float cy = y1 + 0.5f * h, cx = x1 + 0.5f * w;
    const float cy2 = dy * h + cy, cx2 = dx * w + cx;
    const float h2 = expf(dh) * h, w2 = expf(dw) * w;
    float by1 = fminf(fmaxf(cy2 - 0.5f * h2, 0.0f), (float)HFE);
    float bx1 = fminf(fmaxf(cx2 - 0.5f * w2, 0.0f), (float)WFE);
    float by2 = fminf(fmaxf(cy2 + 0.5f * h2, 0.0f), (float)HFE);
    float bx2 = fminf(fmaxf(cx2 + 0.5f * w2, 0.0f), (float)WFE);
    g_kept[l][0] = by1; g_kept[l][1] = bx1;
    g_kept[l][2] = by2; g_kept[l][3] = bx2;
    if (l == HUMAN_LBL) {
        g_hbox[0] = by1; g_hbox[1] = bx1;
        g_hbox[2] = by2; g_hbox[3] = bx2;
    }
}

// ---------------------------------------------------------------------------
// roipool for one output element (same math as reference)
// ---------------------------------------------------------------------------
__device__ __forceinline__ float roipool_one(const float* __restrict__ x, int idx)
{
    const int c  = idx / 49;
    const int ph = (idx % 49) / 7;
    const int pw = idx % 7;

    const float y1 = g_hbox[0], x1 = g_hbox[1], y2 = g_hbox[2], x2 = g_hbox[3];
    const int xmin = (int)rintf(x1 * 0.0625f);
    const int ymin = (int)rintf(y1 * 0.0625f);
    const int xmax = (int)rintf(x2 * 0.0625f);
    const int ymax = (int)rintf(y2 * 0.0625f);
    const float rw = (float)max(xmax - xmin + 1, 1);
    const float rh = (float)max(ymax - ymin + 1, 1);

    int hs = ymin + (int)floorf((float)ph * rh / 7.0f);
    int he = ymin + (int)ceilf((float)(ph + 1) * rh / 7.0f);
    int ws = xmin + (int)floorf((float)pw * rw / 7.0f);
    int we = xmin + (int)ceilf((float)(pw + 1) * rw / 7.0f);
    hs = min(max(hs, 0), HFE); he = min(max(he, 0), HFE);
    ws = min(max(ws, 0), WFE); we = min(max(we, 0), WFE);

    float m = -1e30f;
    for (int yy = hs; yy < he; yy++)
        for (int xx = ws; xx < we; xx++)
            m = fmaxf(m, x[c * (HFE * WFE) + yy * WFE + xx]);
    return (hs < he && ws < we) ? ((m <= -0.5e30f) ? 0.0f : m) : 0.0f;
}

// ---------------------------------------------------------------------------
// Kernel 2: GEMV1 split-K with fused roipool prologue.
// grid (8, 256) = 2048 blocks, 128 threads. W1 streamed evict-first.
// ---------------------------------------------------------------------------
__global__ void k_gemv1(const float4* __restrict__ W1,
                        const float*  __restrict__ x)
{
    cudaGridDependencySynchronize();

    const int t  = threadIdx.x;
    const int i0 = blockIdx.y * ROWS1;

    __shared__ float sf[ROWS1];
    if (t < ROWS1) sf[t] = roipool_one(x, i0 + t);
    __syncthreads();

    const int j4 = blockIdx.x * 128 + t;
    float4 acc = make_float4(0.f, 0.f, 0.f, 0.f);
    const float4* __restrict__ w = W1 + (size_t)i0 * DH4 + j4;
    #pragma unroll 7
    for (int i = 0; i < ROWS1; i++) {
        const float4 v = __ldcs(&w[(size_t)i * DH4]);
        const float  s = sf[i];
        acc.x += s * v.x; acc.y += s * v.y;
        acc.z += s * v.z; acc.w += s * v.w;
    }
    g_part1[blockIdx.y * DH4 + j4] = acc;
}

// ---------------------------------------------------------------------------
// Kernel 3: reduce1, block-spread version. 256 blocks x 256 threads.
// Block owns 4 float4 columns. Thread (jl4 = t&3, kq = t>>2) sums 4 partials;
// 6-step smem tree over the 64 kq groups.
// ---------------------------------------------------------------------------
__global__ void k_reduce1(const float4* __restrict__ b1)
{
    cudaGridDependencySynchronize();

    const int t   = threadIdx.x;
    const int jl4 = t & 3;
    const int kq  = t >> 2;                  // 0..63
    const int j4  = blockIdx.x * 4 + jl4;

    float4 a = make_float4(0.f, 0.f, 0.f, 0.f);
    #pragma unroll
    for (int k = 0; k < SPLIT1 / 64; k++) {  // 4 independent loads
        const float4 v = g_part1[(size_t)(kq * (SPLIT1 / 64) + k) * DH4 + j4];
        a.x += v.x; a.y += v.y; a.z += v.z; a.w += v.w;
    }

    __shared__ float4 sm[64][4];
    sm[kq][jl4] = a;
    __syncthreads();
    for (int st = 32; st >= 1; st >>= 1) {
        if (kq < st) {
            const float4 v = sm[kq + st][jl4];
            sm[kq][jl4].x += v.x; sm[kq][jl4].y += v.y;
            sm[kq][jl4].z += v.z; sm[kq][jl4].w += v.w;
        }
        __syncthreads();
    }

    if (t < 4) {
        const int jj4 = blockIdx.x * 4 + t;
        float4 s = b1[jj4];
        const float4 v = sm[0][t];
        s.x = fmaxf(s.x + v.x, 0.f); s.y = fmaxf(s.y + v.y, 0.f);
        s.z = fmaxf(s.z + v.z, 0.f); s.w = fmaxf(s.w + v.w, 0.f);
        g_h1f4[jj4] = s;
    }
}

// ---------------------------------------------------------------------------
// Kernel 4: GEMV2 split-K with COMPACTED ReLU zero-skip.
// grid (8, 256) = 2048 blocks, 128 threads.
// Nonzero rows are compacted into smem (ascending order => bit-identical
// accumulation order), then the loop issues UNCONDITIONAL loads over the
// compacted list — restores MLP that the per-row branch destroyed.
// ---------------------------------------------------------------------------
__global__ void k_gemv2(const float4* __restrict__ W2)
{
    cudaGridDependencySynchronize();

    const int t  = threadIdx.x;
    const int j4 = blockIdx.x * 128 + t;
    const int i0 = blockIdx.y * ROWS2;
    const float* h1 = (const float*)g_h1f4;

    __shared__ float sf[ROWS2];
    __shared__ float sval[ROWS2];
    __shared__ int   sidx[ROWS2];
    __shared__ int   snnz;

    if (t < ROWS2) sf[t] = h1[i0 + t];
    __syncthreads();
    if (t == 0) {                            // tiny serial compaction (16)
        int n = 0;
        #pragma unroll
        for (int i = 0; i < ROWS2; i++) {
            const float s = sf[i];
            if (s != 0.0f) { sidx[n] = i; sval[n] = s; n++; }
        }
        snnz = n;
    }
    __syncthreads();
    const int nnz = snnz;

    float4 acc = make_float4(0.f, 0.f, 0.f, 0.f);
    const float4* __restrict__ w = W2 + (size_t)i0 * DH4 + j4;

    int i = 0;
    for (; i + 4 <= nnz; i += 4) {           // batched: 4 loads in flight
        const float4 v0 = __ldcs(&w[(size_t)sidx[i]     * DH4]);
        const float4 v1 = __ldcs(&w[(size_t)sidx[i + 1] * DH4]);
        const float4 v2 = __ldcs(&w[(size_t)sidx[i + 2] * DH4]);
        const float4 v3 = __ldcs(&w[(size_t)sidx[i + 3] * DH4]);
        const float s0 = sval[i],     s1 = sval[i + 1];
        const float s2 = sval[i + 2], s3 = sval[i + 3];
        // accumulate in ascending row order (same order as the branch loop)
        acc.x += s0 * v0.x; acc.y += s0 * v0.y; acc.z += s0 * v0.z; acc.w += s0 * v0.w;
        acc.x += s1 * v1.x; acc.y += s1 * v1.y; acc.z += s1 * v1.z; acc.w += s1 * v1.w;
        acc.x += s2 * v2.x; acc.y += s2 * v2.y; acc.z += s2 * v2.z; acc.w += s2 * v2.w;
        acc.x += s3 * v3.x; acc.y += s3 * v3.y; acc.z += s3 * v3.z; acc.w += s3 * v3.w;
    }
    for (; i < nnz; i++) {
        const float4 v = __ldcs(&w[(size_t)sidx[i] * DH4]);
        const float  s = sval[i];
        acc.x += s * v.x; acc.y += s * v.y;
        acc.z += s * v.z; acc.w += s * v.w;
    }
    g_part2[blockIdx.y * DH4 + j4] = acc;
}

// ---------------------------------------------------------------------------
// Kernel 5: fused reduce2 + heads partials. 256 blocks x 256 threads.
// Phase 1: block-spread rebuild of a 16-entry fc7 slice (4 float4 columns).
// Phase 2: 31 partial dot products against the (L2-prefetched) head weights.
// ---------------------------------------------------------------------------
__global__ void k_hred(const float4* __restrict__ b2,
                       const float* __restrict__ Wloc,
                       const float* __restrict__ Wact)
{
    cudaGridDependencySynchronize();

    const int t  = threadIdx.x;
    const int j0 = blockIdx.x * 16;          // first fc7 index of this block

    __shared__ float4 sm4[64][4];
    __shared__ float  fc7s[16];

    {   // phase 1: thread (jl4 = t&3, kq = t>>2) sums 4 float4 partials
        const int jl4 = t & 3;
        const int kq  = t >> 2;
        const int j4  = blockIdx.x * 4 + jl4;
        float4 a = make_float4(0.f, 0.f, 0.f, 0.f);
        #pragma unroll
        for (int k = 0; k < SPLIT2 / 64; k++) {
            const float4 v = g_part2[(size_t)(kq * (SPLIT2 / 64) + k) * DH4 + j4];
            a.x += v.x; a.y += v.y; a.z += v.z; a.w += v.w;
        }
        sm4[kq][jl4] = a;
    }
    __syncthreads();
    {
        const int jl4 = t & 3;
        const int kq  = t >> 2;
        for (int st = 32; st >= 1; st >>= 1) {
            if (kq < st) {
                const float4 v = sm4[kq + st][jl4];
                sm4[kq][jl4].x += v.x; sm4[kq][jl4].y += v.y;
                sm4[kq][jl4].z += v.z; sm4[kq][jl4].w += v.w;
            }
            __syncthreads();
        }
    }
    if (t < 4) {
        const int j4 = blockIdx.x * 4 + t;
        float4 s = b2[j4];
        const float4 v = sm4[0][t];
        fc7s[t * 4 + 0] = fmaxf(s.x + v.x, 0.f);
        fc7s[t * 4 + 1] = fmaxf(s.y + v.y, 0.f);
        fc7s[t * 4 + 2] = fmaxf(s.z + v.z, 0.f);
        fc7s[t * 4 + 3] = fmaxf(s.w + v.w, 0.f);
    }
    __syncthreads();

    // phase 2: partial dots. thread t -> (o = t/8, q = t%8), 2 terms each.
    __shared__ float sp[31][8];
    const int o = t >> 3;
    const int q = t & 7;
    if (o < 31) {
        float p = 0.0f;
        #pragma unroll
        for (int m = 0; m < 2; m++) {
            const int idx = q * 2 + m;
            const float f = fc7s[idx];
            p += (o < 4) ? f * Wloc[(j0 + idx) * 4 + o]
                         : f * Wact[(j0 + idx) * NACT + (o - 4)];
        }
        sp[o][q] = p;
    }
    __syncthreads();
    if (o < 31 && q == 0) {
        float s = 0.0f;
        #pragma unroll
        for (int m = 0; m < 8; m++) s += sp[o][m];
        g_hp[blockIdx.x * 31 + o] = s;
    }
}

// ---------------------------------------------------------------------------
// Kernel 6: final — sum head partials (2-stage), gaussian pick, assemble.
// 1 block, 256 threads: (o = t&31, chunk = t>>5) covers 31 outputs x 8 chunks.
// ---------------------------------------------------------------------------
__global__ void k_final(const float* __restrict__ bloc,
                        const float* __restrict__ bact,
                        const int*   __restrict__ imgshape,
                        float* __restrict__ out)
{
    cudaGridDependencySynchronize();

    const int t = threadIdx.x;
    const int o = t & 31;
    const int c = t >> 5;                    // 0..7
    __shared__ float sp2[8][32];
    __shared__ float locs[4];

    {
        float s = 0.0f;
        if (o < 31) {
            #pragma unroll 4
            for (int b = c * (HB / 8); b < (c + 1) * (HB / 8); b++)
                s += g_hp[b * 31 + o];
        }
        sp2[c][o] = s;
    }
    __syncthreads();
    if (t < 31) {
        float s = (t < 4) ? bloc[t] : bact[t - 4];
        #pragma unroll
        for (int m = 0; m < 8; m++) s += sp2[m][t];
        if (t < 4) locs[t] = s;
        else       out[8 + (t - 4)] = s;     // action scores
    }
    __syncthreads();
    if (t != 0) return;

    const float img0 = (float)imgshape[0];
    const float img1 = (float)imgshape[1];

    const float hb0 = g_hbox[0], hb1 = g_hbox[1], hb2 = g_hbox[2], hb3 = g_hbox[3];
    const float hw_ = hb3 - hb1, hh_ = hb2 - hb0;
    const float h4x = 0.5f * hw_, h4y = 0.5f * hh_;
    const float hw = fmaxf(hw_, 1e-3f), hh = fmaxf(hh_, 1e-3f);

    const float mw = locs[3] - locs[1], mh = locs[2] - locs[0];
    const float mu0 = 0.5f * mw, mu1 = 0.5f * mh, mu2 = mw, mu3 = mh;

    float best = -1.0f;
    int   bl   = 0;
    for (int l = 0; l < 20; l++) {
        if (l == HUMAN_LBL) continue;
        const float b0 = g_kept[l][0], b1 = g_kept[l][1];
        const float b2 = g_kept[l][2], b3 = g_kept[l][3];
        const float cw_ = b3 - b1, ch_ = b2 - b0;
        const float cx = 0.5f * cw_, cy = 0.5f * ch_;
        const float cw = fmaxf(cw_, 1e-3f), ch = fmaxf(ch_, 1e-3f);
        const float d0 = (cx - h4x) / hw - mu0;
        const float d1 = (cy - h4y) / hh - mu1;
        const float d2 = logf(cw / hw) - mu2;
        const float d3 = logf(ch / hh) - mu3;
        const float gau = expf(-(d0*d0 + d1*d1 + d2*d2 + d3*d3) /
                               (2.0f * 0.3f * 0.3f));
        if (gau > best) { best = gau; bl = l; }
    }

    const float invy = img0 / (float)HFE;
    const float invx = img1 / (float)WFE;
    out[0] = hb0 * invy; out[1] = hb1 * invx;
    out[2] = hb2 * invy; out[3] = hb3 * invx;
    out[4] = g_kept[bl][0] * invy; out[5] = g_kept[bl][1] * invx;
    out[6] = g_kept[bl][2] * invy; out[7] = g_kept[bl][3] * invx;
    out[35] = (float)HFE / img0;
}

// ---------------------------------------------------------------------------
// PDL launch helper
// ---------------------------------------------------------------------------
static void launch_pdl(const void* func, dim3 grid, dim3 block, void** args)
{
    cudaLaunchConfig_t cfg = {};
    cfg.gridDim  = grid;
    cfg.blockDim = block;
    cudaLaunchAttribute attr[1];
    attr[0].id = cudaLaunchAttributeProgrammaticStreamSerialization;
    attr[0].val.programmaticStreamSerializationAllowed = 1;
    cfg.attrs = attr;
    cfg.numAttrs = 1;
    cudaLaunchKernelExC(&cfg, func, args);
}

// ---------------------------------------------------------------------------
extern "C" void kernel_launch(void* const* d_in, const int* in_sizes, int n_in,
                              void* d_out, int out_size)
{
    const float* x        = (const float*)d_in[0];
    const float* pscores  = (const float*)d_in[1];
    const float* poff     = (const float*)d_in[2];
    const float* rois     = (const float*)d_in[3];
    const int*   imgshape = (const int*)  d_in[4];
    const float* W1f      = (const float*)d_in[5];
    const float* b1f      = (const float*)d_in[6];
    const float* W2f      = (const float*)d_in[7];
    const float* b2f      = (const float*)d_in[8];
    const float* Wloc     = (const float*)d_in[9];
    const float* bloc     = (const float*)d_in[10];
    const float* Wact     = (const float*)d_in[11];
    const float* bact     = (const float*)d_in[12];
    float* out = (float*)d_out;
    const float4* W1 = (const float4*)W1f;
    const float4* W2 = (const float4*)W2f;
    const float4* b1 = (const float4*)b1f;
    const float4* b2 = (const float4*)b2f;

    {   void* a[] = {(void*)&pscores, (void*)&Wloc, (void*)&Wact};
        launch_pdl((const void*)k_selA, dim3(SELC, 21), dim3(256), a); }
    {   void* a[] = {(void*)&poff, (void*)&rois, (void*)&imgshape};
        launch_pdl((const void*)k_selB, dim3(1), dim3(32), a); }
    {   void* a[] = {(void*)&W1, (void*)&x};
        launch_pdl((const void*)k_gemv1, dim3(8, SPLIT1), dim3(128), a); }
    {   void* a[] = {(void*)&b1};
        launch_pdl((const void*)k_reduce1, dim3(256), dim3(256), a); }
    {   void* a[] = {(void*)&W2};
        launch_pdl((const void*)k_gemv2, dim3(8, SPLIT2), dim3(128), a); }
    {   void* a[] = {(void*)&b2, (void*)&Wloc, (void*)&Wact};
        launch_pdl((const void*)k_hred, dim3(HB), dim3(256), a); }
    {   void* a[] = {(void*)&bloc, (void*)&bact, (void*)&imgshape, (void*)&out};
        launch_pdl((const void*)k_final, dim3(1), dim3(256), a); }
}

// round 15
// speedup vs baseline: 1.0312x; 1.0273x over previous
#include <cuda_runtime.h>
#include <math.h>

// ---------------- problem constants -----------------------------------------
#define R_ROIS 2000
#define NOBJ   21
#define HFE    38
#define WFE    50
#define D1     25088        // 512*7*7
#define DH     4096
#define DH4    (DH/4)
#define NACT   27
#define HUMAN_LBL 14

#define SPLIT1 256
#define ROWS1  (D1/SPLIT1)  // 98
#define SPLIT2 256
#define ROWS2  (DH/SPLIT2)  // 16
#define SELC   8            // roi chunks in select stage A
#define HB     256          // hred blocks

// ---------------- device scratch --------------------------------------------
__device__ float  g_selv[20][SELC];
__device__ int    g_seli[20][SELC];
__device__ float4 g_part1[SPLIT1 * DH4];
__device__ float4 g_h1f4[DH4];
__device__ float4 g_part2[SPLIT2 * DH4];
__device__ float  g_hp[HB * 31];     // per-block head partials
__device__ float  g_sink[16];        // prefetch DCE guard

// ---------------------------------------------------------------------------
// device helper: chunk-argmax for one label + box decode (selB math, inlined
// at every consumer — redundant but trivial; removes the selB graph node).
// ---------------------------------------------------------------------------
__device__ __forceinline__ void decode_label_box(
    int l, const float* __restrict__ off, const float* __restrict__ rois,
    const int* __restrict__ imgshape, float box[4])
{
    const int cls = l + 1;
    float best = -1e30f;
    int   r    = 0x7fffffff;
    #pragma unroll
    for (int c = 0; c < SELC; c++) {        // ascending chunks + strict >
        const float v = g_selv[l][c];       // == global first-max semantics
        if (v > best) { best = v; r = g_seli[l][c]; }
    }

    const float img0 = (float)imgshape[0];
    const float img1 = (float)imgshape[1];
    const float sy = (float)HFE / img0;
    const float sx = (float)WFE / img1;
    const float y1 = rois[r * 4 + 0] * sy;
    const float x1 = rois[r * 4 + 1] * sx;
    const float y2 = rois[r * 4 + 2] * sy;
    const float x2 = rois[r * 4 + 3] * sx;
    const float dy = off[r * (NOBJ * 4) + cls * 4 + 0] * 0.1f;
    const float dx = off[r * (NOBJ * 4) + cls * 4 + 1] * 0.1f;
    const float dh = off[r * (NOBJ * 4) + cls * 4 + 2] * 0.2f;
    const float dw = off[r * (NOBJ * 4) + cls * 4 + 3] * 0.2f;
    const float h  = y2 - y1, w = x2 - x1;
    const float cy = y1 + 0.5f * h, cx = x1 + 0.5f * w;
    const float cy2 = dy * h + cy, cx2 = dx * w + cx;
    const float h2 = expf(dh) * h, w2 = expf(dw) * w;
    box[0] = fminf(fmaxf(cy2 - 0.5f * h2, 0.0f), (float)HFE);
    box[1] = fminf(fmaxf(cx2 - 0.5f * w2, 0.0f), (float)WFE);
    box[2] = fminf(fmaxf(cy2 + 0.5f * h2, 0.0f), (float)HFE);
    box[3] = fminf(fmaxf(cx2 + 0.5f * w2, 0.0f), (float)WFE);
}

// ---------------------------------------------------------------------------
// Kernel 1: select stage A — per-(label, roi-chunk) partial argmax of
// softmax prob (NMS_T=0 => greedy NMS keeps only the top-1 box per class).
// grid (SELC, 21): by<20 = labels; by==20 = Wloc/Wact L2 prefetch row.
// ---------------------------------------------------------------------------
__global__ void k_selA(const float* __restrict__ scores,
                       const float* __restrict__ Wloc,
                       const float* __restrict__ Wact)
{
    cudaGridDependencySynchronize();
    const int t = threadIdx.x;

    if (blockIdx.y == 20) {
        const float4* wl = (const float4*)Wloc;   // 4096 float4
        const float4* wa = (const float4*)Wact;   // 27648 float4
        float acc = 0.0f;
        for (int i = blockIdx.x * 256 + t; i < 4096;  i += SELC * 256) {
            const float4 v = __ldg(&wl[i]); acc += v.x + v.y + v.z + v.w;
        }
        for (int i = blockIdx.x * 256 + t; i < 27648; i += SELC * 256) {
            const float4 v = __ldg(&wa[i]); acc += v.x + v.y + v.z + v.w;
        }
        if (acc == 1e30f) g_sink[blockIdx.x] = acc;  // never true; defeats DCE
        return;
    }

    const int l   = blockIdx.y;
    const int cls = l + 1;
    const int r   = blockIdx.x * 256 + t;

    float best  = -1e30f;
    int   bestr = 0x7fffffff;
    if (r < R_ROIS) {
        const float* s = scores + r * NOBJ;
        float mx = s[0];
        #pragma unroll
        for (int j = 1; j < NOBJ; j++) mx = fmaxf(mx, s[j]);
        float sum = 0.0f;
        #pragma unroll
        for (int j = 0; j < NOBJ; j++) sum += expf(s[j] - mx);
        best  = s[cls] - (mx + logf(sum));
        bestr = r;
    }

    __shared__ float sb[256];
    __shared__ int   si[256];
    sb[t] = best; si[t] = bestr;
    __syncthreads();
    for (int st = 128; st > 0; st >>= 1) {
        if (t < st) {
            float ob = sb[t + st]; int oi = si[t + st];
            if (ob > sb[t] || (ob == sb[t] && oi < si[t])) { sb[t] = ob; si[t] = oi; }
        }
        __syncthreads();
    }
    if (t == 0) { g_selv[l][blockIdx.x] = sb[0]; g_seli[l][blockIdx.x] = si[0]; }
}

// ---------------------------------------------------------------------------
// roipool for one output element (same math as reference); hbox via smem
// ---------------------------------------------------------------------------
__device__ __forceinline__ float roipool_one(const float* __restrict__ x, int idx,
                                             const float* __restrict__ hb)
{
    const int c  = idx / 49;
    const int ph = (idx % 49) / 7;
    const int pw = idx % 7;

    const float y1 = hb[0], x1 = hb[1], y2 = hb[2], x2 = hb[3];
    const int xmin = (int)rintf(x1 * 0.0625f);
    const int ymin = (int)rintf(y1 * 0.0625f);
    const int xmax = (int)rintf(x2 * 0.0625f);
    const int ymax = (int)rintf(y2 * 0.0625f);
    const float rw = (float)max(xmax - xmin + 1, 1);
    const float rh = (float)max(ymax - ymin + 1, 1);

    int hs = ymin + (int)floorf((float)ph * rh / 7.0f);
    int he = ymin + (int)ceilf((float)(ph + 1) * rh / 7.0f);
    int ws = xmin + (int)floorf((float)pw * rw / 7.0f);
    int we = xmin + (int)ceilf((float)(pw + 1) * rw / 7.0f);
    hs = min(max(hs, 0), HFE); he = min(max(he, 0), HFE);
    ws = min(max(ws, 0), WFE); we = min(max(we, 0), WFE);

    float m = -1e30f;
    for (int yy = hs; yy < he; yy++)
        for (int xx = ws; xx < we; xx++)
            m = fmaxf(m, x[c * (HFE * WFE) + yy * WFE + xx]);
    return (hs < he && ws < we) ? ((m <= -0.5e30f) ? 0.0f : m) : 0.0f;
}

// ---------------------------------------------------------------------------
// Kernel 2: GEMV1 split-K with fused human-box decode + roipool prologue.
// grid (8, 256) = 2048 blocks, 128 threads. Gridsyncs directly on selA
// (the selB node is gone — every block recomputes the human box itself).
// ---------------------------------------------------------------------------
__global__ void k_gemv1(const float4* __restrict__ W1,
                        const float*  __restrict__ x,
                        const float*  __restrict__ off,
                        const float*  __restrict__ rois,
                        const int*    __restrict__ imgshape)
{
    cudaGridDependencySynchronize();   // selA's g_selv/g_seli ready

    const int t  = threadIdx.x;
    const int i0 = blockIdx.y * ROWS1;

    __shared__ float hb[4];
    if (t == 0) {
        float box[4];
        decode_label_box(HUMAN_LBL, off, rois, imgshape, box);
        hb[0] = box[0]; hb[1] = box[1]; hb[2] = box[2]; hb[3] = box[3];
    }
    __syncthreads();

    __shared__ float sf[ROWS1];
    if (t < ROWS1) sf[t] = roipool_one(x, i0 + t, hb);
    __syncthreads();

    const int j4 = blockIdx.x * 128 + t;
    float4 acc = make_float4(0.f, 0.f, 0.f, 0.f);
    const float4* __restrict__ w = W1 + (size_t)i0 * DH4 + j4;
    #pragma unroll 7
    for (int i = 0; i < ROWS1; i++) {
        const float4 v = __ldcs(&w[(size_t)i * DH4]);
        const float  s = sf[i];
        acc.x += s * v.x; acc.y += s * v.y;
        acc.z += s * v.z; acc.w += s * v.w;
    }
    g_part1[blockIdx.y * DH4 + j4] = acc;
}

// ---------------------------------------------------------------------------
// Kernel 3: reduce1, block-spread version. 256 blocks x 256 threads.
// ---------------------------------------------------------------------------
__global__ void k_reduce1(const float4* __restrict__ b1)
{
    cudaGridDependencySynchronize();

    const int t   = threadIdx.x;
    const int jl4 = t & 3;
    const int kq  = t >> 2;                  // 0..63
    const int j4  = blockIdx.x * 4 + jl4;

    float4 a = make_float4(0.f, 0.f, 0.f, 0.f);
    #pragma unroll
    for (int k = 0; k < SPLIT1 / 64; k++) {  // 4 independent loads
        const float4 v = g_part1[(size_t)(kq * (SPLIT1 / 64) + k) * DH4 + j4];
        a.x += v.x; a.y += v.y; a.z += v.z; a.w += v.w;
    }

    __shared__ float4 sm[64][4];
    sm[kq][jl4] = a;
    __syncthreads();
    for (int st = 32; st >= 1; st >>= 1) {
        if (kq < st) {
            const float4 v = sm[kq + st][jl4];
            sm[kq][jl4].x += v.x; sm[kq][jl4].y += v.y;
            sm[kq][jl4].z += v.z; sm[kq][jl4].w += v.w;
        }
        __syncthreads();
    }

    if (t < 4) {
        const int jj4 = blockIdx.x * 4 + t;
        float4 s = b1[jj4];
        const float4 v = sm[0][t];
        s.x = fmaxf(s.x + v.x, 0.f); s.y = fmaxf(s.y + v.y, 0.f);
        s.z = fmaxf(s.z + v.z, 0.f); s.w = fmaxf(s.w + v.w, 0.f);
        g_h1f4[jj4] = s;
    }
}

// ---------------------------------------------------------------------------
// Kernel 4: GEMV2 split-K with ReLU zero-skip (exact: ~50% of h1 is 0).
// grid (8, 256) = 2048 blocks, 128 threads. Block-uniform skip, 2KB rows.
// ---------------------------------------------------------------------------
__global__ void k_gemv2(const float4* __restrict__ W2)
{
    cudaGridDependencySynchronize();

    const int t  = threadIdx.x;
    const int j4 = blockIdx.x * 128 + t;
    const int i0 = blockIdx.y * ROWS2;
    const float* h1 = (const float*)g_h1f4;

    __shared__ float sf[ROWS2];
    if (t < ROWS2) sf[t] = h1[i0 + t];
    __syncthreads();

    float4 acc = make_float4(0.f, 0.f, 0.f, 0.f);
    const float4* __restrict__ w = W2 + (size_t)i0 * DH4 + j4;
    #pragma unroll
    for (int i = 0; i < ROWS2; i++) {
        const float s = sf[i];
        if (s != 0.0f) {                   // block-uniform branch
            const float4 v = __ldcs(&w[(size_t)i * DH4]);
            acc.x += s * v.x; acc.y += s * v.y;
            acc.z += s * v.z; acc.w += s * v.w;
        }
    }
    g_part2[blockIdx.y * DH4 + j4] = acc;
}

// ---------------------------------------------------------------------------
// Kernel 5: fused reduce2 + heads partials. 256 blocks x 256 threads.
// ---------------------------------------------------------------------------
__global__ void k_hred(const float4* __restrict__ b2,
                       const float* __restrict__ Wloc,
                       const float* __restrict__ Wact)
{
    cudaGridDependencySynchronize();

    const int t  = threadIdx.x;
    const int j0 = blockIdx.x * 16;          // first fc7 index of this block

    __shared__ float4 sm4[64][4];
    __shared__ float  fc7s[16];

    {   // phase 1: thread (jl4 = t&3, kq = t>>2) sums 4 float4 partials
        const int jl4 = t & 3;
        const int kq  = t >> 2;
        const int j4  = blockIdx.x * 4 + jl4;
        float4 a = make_float4(0.f, 0.f, 0.f, 0.f);
        #pragma unroll
        for (int k = 0; k < SPLIT2 / 64; k++) {
            const float4 v = g_part2[(size_t)(kq * (SPLIT2 / 64) + k) * DH4 + j4];
            a.x += v.x; a.y += v.y; a.z += v.z; a.w += v.w;
        }
        sm4[kq][jl4] = a;
    }
    __syncthreads();
    {
        const int jl4 = t & 3;
        const int kq  = t >> 2;
        for (int st = 32; st >= 1; st >>= 1) {
            if (kq < st) {
                const float4 v = sm4[kq + st][jl4];
                sm4[kq][jl4].x += v.x; sm4[kq][jl4].y += v.y;
                sm4[kq][jl4].z += v.z; sm4[kq][jl4].w += v.w;
            }
            __syncthreads();
        }
    }
    if (t < 4) {
        const int j4 = blockIdx.x * 4 + t;
        float4 s = b2[j4];
        const float4 v = sm4[0][t];
        fc7s[t * 4 + 0] = fmaxf(s.x + v.x, 0.f);
        fc7s[t * 4 + 1] = fmaxf(s.y + v.y, 0.f);
        fc7s[t * 4 + 2] = fmaxf(s.z + v.z, 0.f);
        fc7s[t * 4 + 3] = fmaxf(s.w + v.w, 0.f);
    }
    __syncthreads();

    // phase 2: partial dots. thread t -> (o = t/8, q = t%8), 2 terms each.
    __shared__ float sp[31][8];
    const int o = t >> 3;
    const int q = t & 7;
    if (o < 31) {
        float p = 0.0f;
        #pragma unroll
        for (int m = 0; m < 2; m++) {
            const int idx = q * 2 + m;
            const float f = fc7s[idx];
            p += (o < 4) ? f * Wloc[(j0 + idx) * 4 + o]
                         : f * Wact[(j0 + idx) * NACT + (o - 4)];
        }
        sp[o][q] = p;
    }
    __syncthreads();
    if (o < 31 && q == 0) {
        float s = 0.0f;
        #pragma unroll
        for (int m = 0; m < 8; m++) s += sp[o][m];
        g_hp[blockIdx.x * 31 + o] = s;
    }
}

// ---------------------------------------------------------------------------
// Kernel 6: final — head partial sums (2-stage), inline box decode for all
// 20 labels, gaussian pick, output assembly. 1 block, 256 threads.
// ---------------------------------------------------------------------------
__global__ void k_final(const float* __restrict__ bloc,
                        const float* __restrict__ bact,
                        const float* __restrict__ off,
                        const float* __restrict__ rois,
                        const int*   __restrict__ imgshape,
                        float* __restrict__ out)
{
    cudaGridDependencySynchronize();

    const int t = threadIdx.x;
    const int o = t & 31;
    const int c = t >> 5;                    // 0..7
    __shared__ float sp2[8][32];
    __shared__ float locs[4];
    __shared__ float kbox[20][4];

    {   // head partial sums, stage 1
        float s = 0.0f;
        if (o < 31) {
            #pragma unroll 4
            for (int b = c * (HB / 8); b < (c + 1) * (HB / 8); b++)
                s += g_hp[b * 31 + o];
        }
        sp2[c][o] = s;
    }
    // inline selB: threads 32..51 decode the 20 label boxes (parallel w/ above)
    if (t >= 32 && t < 52) {
        float box[4];
        decode_label_box(t - 32, off, rois, imgshape, box);
        kbox[t - 32][0] = box[0]; kbox[t - 32][1] = box[1];
        kbox[t - 32][2] = box[2]; kbox[t - 32][3] = box[3];
    }
    __syncthreads();
    if (t < 31) {       // head sums, stage 2
        float s = (t < 4) ? bloc[t] : bact[t - 4];
        #pragma unroll
        for (int m = 0; m < 8; m++) s += sp2[m][t];
        if (t < 4) locs[t] = s;
        else       out[8 + (t - 4)] = s;     // action scores
    }
    __syncthreads();
    if (t != 0) return;

    const float img0 = (float)imgshape[0];
    const float img1 = (float)imgshape[1];

    const float hb0 = kbox[HUMAN_LBL][0], hb1 = kbox[HUMAN_LBL][1];
    const float hb2 = kbox[HUMAN_LBL][2], hb3 = kbox[HUMAN_LBL][3];
    const float hw_ = hb3 - hb1, hh_ = hb2 - hb0;
    const float h4x = 0.5f * hw_, h4y = 0.5f * hh_;
    const float hw = fmaxf(hw_, 1e-3f), hh = fmaxf(hh_, 1e-3f);

    const float mw = locs[3] - locs[1], mh = locs[2] - locs[0];
    const float mu0 = 0.5f * mw, mu1 = 0.5f * mh, mu2 = mw, mu3 = mh;

    float best = -1.0f;
    int   bl   = 0;
    for (int l = 0; l < 20; l++) {
        if (l == HUMAN_LBL) continue;
        const float b0 = kbox[l][0], b1 = kbox[l][1];
        const float b2 = kbox[l][2], b3 = kbox[l][3];
        const float cw_ = b3 - b1, ch_ = b2 - b0;
        const float cx = 0.5f * cw_, cy = 0.5f * ch_;
        const float cw = fmaxf(cw_, 1e-3f), ch = fmaxf(ch_, 1e-3f);
        const float d0 = (cx - h4x) / hw - mu0;
        const float d1 = (cy - h4y) / hh - mu1;
        const float d2 = logf(cw / hw) - mu2;
        const float d3 = logf(ch / hh) - mu3;
        const float gau = expf(-(d0*d0 + d1*d1 + d2*d2 + d3*d3) /
                               (2.0f * 0.3f * 0.3f));
        if (gau > best) { best = gau; bl = l; }
    }

    const float invy = img0 / (float)HFE;
    const float invx = img1 / (float)WFE;
    out[0] = hb0 * invy; out[1] = hb1 * invx;
    out[2] = hb2 * invy; out[3] = hb3 * invx;
    out[4] = kbox[bl][0] * invy; out[5] = kbox[bl][1] * invx;
    out[6] = kbox[bl][2] * invy; out[7] = kbox[bl][3] * invx;
    out[35] = (float)HFE / img0;
}

// ---------------------------------------------------------------------------
// PDL launch helper
// ---------------------------------------------------------------------------
static void launch_pdl(const void* func, dim3 grid, dim3 block, void** args)
{
    cudaLaunchConfig_t cfg = {};
    cfg.gridDim  = grid;
    cfg.blockDim = block;
    cudaLaunchAttribute attr[1];
    attr[0].id = cudaLaunchAttributeProgrammaticStreamSerialization;
    attr[0].val.programmaticStreamSerializationAllowed = 1;
    cfg.attrs = attr;
    cfg.numAttrs = 1;
    cudaLaunchKernelExC(&cfg, func, args);
}

// ---------------------------------------------------------------------------
extern "C" void kernel_launch(void* const* d_in, const int* in_sizes, int n_in,
                              void* d_out, int out_size)
{
    const float* x        = (const float*)d_in[0];
    const float* pscores  = (const float*)d_in[1];
    const float* poff     = (const float*)d_in[2];
    const float* rois     = (const float*)d_in[3];
    const int*   imgshape = (const int*)  d_in[4];
    const float* W1f      = (const float*)d_in[5];
    const float* b1f      = (const float*)d_in[6];
    const float* W2f      = (const float*)d_in[7];
    const float* b2f      = (const float*)d_in[8];
    const float* Wloc     = (const float*)d_in[9];
    const float* bloc     = (const float*)d_in[10];
    const float* Wact     = (const float*)d_in[11];
    const float* bact     = (const float*)d_in[12];
    float* out = (float*)d_out;
    const float4* W1 = (const float4*)W1f;
    const float4* W2 = (const float4*)W2f;
    const float4* b1 = (const float4*)b1f;
    const float4* b2 = (const float4*)b2f;

    {   void* a[] = {(void*)&pscores, (void*)&Wloc, (void*)&Wact};
        launch_pdl((const void*)k_selA, dim3(SELC, 21), dim3(256), a); }
    {   void* a[] = {(void*)&W1, (void*)&x, (void*)&poff, (void*)&rois,
                     (void*)&imgshape};
        launch_pdl((const void*)k_gemv1, dim3(8, SPLIT1), dim3(128), a); }
    {   void* a[] = {(void*)&b1};
        launch_pdl((const void*)k_reduce1, dim3(256), dim3(256), a); }
    {   void* a[] = {(void*)&W2};
        launch_pdl((const void*)k_gemv2, dim3(8, SPLIT2), dim3(128), a); }
    {   void* a[] = {(void*)&b2, (void*)&Wloc, (void*)&Wact};
        launch_pdl((const void*)k_hred, dim3(HB), dim3(256), a); }
    {   void* a[] = {(void*)&bloc, (void*)&bact, (void*)&poff, (void*)&rois,
                     (void*)&imgshape, (void*)&out};
        launch_pdl((const void*)k_final, dim3(1), dim3(256), a); }
}

// round 16
// speedup vs baseline: 1.0395x; 1.0081x over previous
#include <cuda_runtime.h>
#include <math.h>

// ---------------- problem constants -----------------------------------------
#define R_ROIS 2000
#define NOBJ   21
#define HFE    38
#define WFE    50
#define D1     25088        // 512*7*7
#define DH     4096
#define DH4    (DH/4)
#define NACT   27
#define HUMAN_LBL 14

#define SPLIT1 256
#define ROWS1  (D1/SPLIT1)  // 98
#define SPLIT2 256
#define ROWS2  (DH/SPLIT2)  // 16
#define SELC   8            // roi chunks in select stage A
#define HB     256          // hred blocks
#define NGRP   (DH/ROWS2)   // 256 h1 groups of 16

// ---------------- device scratch --------------------------------------------
__device__ float  g_selv[20][SELC];
__device__ int    g_seli[20][SELC];
__device__ float4 g_part1[SPLIT1 * DH4];
__device__ float4 g_part2[SPLIT2 * DH4];
__device__ int    g_nnz [NGRP];           // compacted h1 per 16-row group
__device__ int    g_cidx[NGRP][ROWS2];
__device__ float  g_cval[NGRP][ROWS2];
__device__ float  g_hp[HB * 31];          // per-block head partials
__device__ float  g_sink[16];             // prefetch DCE guard

// ---------------------------------------------------------------------------
// device helper: chunk-argmax for one label + box decode (selB math, inlined
// at every consumer — removes the selB graph node).
// ---------------------------------------------------------------------------
__device__ __forceinline__ void decode_label_box(
    int l, const float* __restrict__ off, const float* __restrict__ rois,
    const int* __restrict__ imgshape, float box[4])
{
    const int cls = l + 1;
    float best = -1e30f;
    int   r    = 0x7fffffff;
    #pragma unroll
    for (int c = 0; c < SELC; c++) {        // ascending chunks + strict >
        const float v = g_selv[l][c];       // == global first-max semantics
        if (v > best) { best = v; r = g_seli[l][c]; }
    }

    const float img0 = (float)imgshape[0];
    const float img1 = (float)imgshape[1];
    const float sy = (float)HFE / img0;
    const float sx = (float)WFE / img1;
    const float y1 = rois[r * 4 + 0] * sy;
    const float x1 = rois[r * 4 + 1] * sx;
    const float y2 = rois[r * 4 + 2] * sy;
    const float x2 = rois[r * 4 + 3] * sx;
    const float dy = off[r * (NOBJ * 4) + cls * 4 + 0] * 0.1f;
    const float dx = off[r * (NOBJ * 4) + cls * 4 + 1] * 0.1f;
    const float dh = off[r * (NOBJ * 4) + cls * 4 + 2] * 0.2f;
    const float dw = off[r * (NOBJ * 4) + cls * 4 + 3] * 0.2f;
    const float h  = y2 - y1, w = x2 - x1;
    const float cy = y1 + 0.5f * h, cx = x1 + 0.5f * w;
    const float cy2 = dy * h + cy, cx2 = dx * w + cx;
    const float h2 = expf(dh) * h, w2 = expf(dw) * w;
    box[0] = fminf(fmaxf(cy2 - 0.5f * h2, 0.0f), (float)HFE);
    box[1] = fminf(fmaxf(cx2 - 0.5f * w2, 0.0f), (float)WFE);
    box[2] = fminf(fmaxf(cy2 + 0.5f * h2, 0.0f), (float)HFE);
    box[3] = fminf(fmaxf(cx2 + 0.5f * w2, 0.0f), (float)WFE);
}

// ---------------------------------------------------------------------------
// Kernel 1: select stage A — per-(label, roi-chunk) partial argmax of
// softmax prob (NMS_T=0 => greedy NMS keeps only the top-1 box per class).
// grid (SELC, 21): by<20 = labels; by==20 = Wloc/Wact L2 prefetch row.
// ---------------------------------------------------------------------------
__global__ void k_selA(const float* __restrict__ scores,
                       const float* __restrict__ Wloc,
                       const float* __restrict__ Wact)
{
    cudaGridDependencySynchronize();
    const int t = threadIdx.x;

    if (blockIdx.y == 20) {
        const float4* wl = (const float4*)Wloc;   // 4096 float4
        const float4* wa = (const float4*)Wact;   // 27648 float4
        float acc = 0.0f;
        for (int i = blockIdx.x * 256 + t; i < 4096;  i += SELC * 256) {
            const float4 v = __ldg(&wl[i]); acc += v.x + v.y + v.z + v.w;
        }
        for (int i = blockIdx.x * 256 + t; i < 27648; i += SELC * 256) {
            const float4 v = __ldg(&wa[i]); acc += v.x + v.y + v.z + v.w;
        }
        if (acc == 1e30f) g_sink[blockIdx.x] = acc;  // never true; defeats DCE
        return;
    }

    const int l   = blockIdx.y;
    const int cls = l + 1;
    const int r   = blockIdx.x * 256 + t;

    float best  = -1e30f;
    int   bestr = 0x7fffffff;
    if (r < R_ROIS) {
        const float* s = scores + r * NOBJ;
        float mx = s[0];
        #pragma unroll
        for (int j = 1; j < NOBJ; j++) mx = fmaxf(mx, s[j]);
        float sum = 0.0f;
        #pragma unroll
        for (int j = 0; j < NOBJ; j++) sum += expf(s[j] - mx);
        best  = s[cls] - (mx + logf(sum));
        bestr = r;
    }

    __shared__ float sb[256];
    __shared__ int   si[256];
    sb[t] = best; si[t] = bestr;
    __syncthreads();
    for (int st = 128; st > 0; st >>= 1) {
        if (t < st) {
            float ob = sb[t + st]; int oi = si[t + st];
            if (ob > sb[t] || (ob == sb[t] && oi < si[t])) { sb[t] = ob; si[t] = oi; }
        }
        __syncthreads();
    }
    if (t == 0) { g_selv[l][blockIdx.x] = sb[0]; g_seli[l][blockIdx.x] = si[0]; }
}

// ---------------------------------------------------------------------------
// roipool for one output element (same math as reference); hbox via smem
// ---------------------------------------------------------------------------
__device__ __forceinline__ float roipool_one(const float* __restrict__ x, int idx,
                                             const float* __restrict__ hb)
{
    const int c  = idx / 49;
    const int ph = (idx % 49) / 7;
    const int pw = idx % 7;

    const float y1 = hb[0], x1 = hb[1], y2 = hb[2], x2 = hb[3];
    const int xmin = (int)rintf(x1 * 0.0625f);
    const int ymin = (int)rintf(y1 * 0.0625f);
    const int xmax = (int)rintf(x2 * 0.0625f);
    const int ymax = (int)rintf(y2 * 0.0625f);
    const float rw = (float)max(xmax - xmin + 1, 1);
    const float rh = (float)max(ymax - ymin + 1, 1);

    int hs = ymin + (int)floorf((float)ph * rh / 7.0f);
    int he = ymin + (int)ceilf((float)(ph + 1) * rh / 7.0f);
    int ws = xmin + (int)floorf((float)pw * rw / 7.0f);
    int we = xmin + (int)ceilf((float)(pw + 1) * rw / 7.0f);
    hs = min(max(hs, 0), HFE); he = min(max(he, 0), HFE);
    ws = min(max(ws, 0), WFE); we = min(max(we, 0), WFE);

    float m = -1e30f;
    for (int yy = hs; yy < he; yy++)
        for (int xx = ws; xx < we; xx++)
            m = fmaxf(m, x[c * (HFE * WFE) + yy * WFE + xx]);
    return (hs < he && ws < we) ? ((m <= -0.5e30f) ? 0.0f : m) : 0.0f;
}

// ---------------------------------------------------------------------------
// Kernel 2: GEMV1 split-K with fused human-box decode + roipool prologue.
// grid (8, 256) = 2048 blocks, 128 threads. Gridsyncs directly on selA.
// ---------------------------------------------------------------------------
__global__ void k_gemv1(const float4* __restrict__ W1,
                        const float*  __restrict__ x,
                        const float*  __restrict__ off,
                        const float*  __restrict__ rois,
                        const int*    __restrict__ imgshape)
{
    cudaGridDependencySynchronize();   // selA's g_selv/g_seli ready

    const int t  = threadIdx.x;
    const int i0 = blockIdx.y * ROWS1;

    __shared__ float hb[4];
    if (t == 0) {
        float box[4];
        decode_label_box(HUMAN_LBL, off, rois, imgshape, box);
        hb[0] = box[0]; hb[1] = box[1]; hb[2] = box[2]; hb[3] = box[3];
    }
    __syncthreads();

    __shared__ float sf[ROWS1];
    if (t < ROWS1) sf[t] = roipool_one(x, i0 + t, hb);
    __syncthreads();

    const int j4 = blockIdx.x * 128 + t;
    float4 acc = make_float4(0.f, 0.f, 0.f, 0.f);
    const float4* __restrict__ w = W1 + (size_t)i0 * DH4 + j4;
    #pragma unroll 7
    for (int i = 0; i < ROWS1; i++) {
        const float4 v = __ldcs(&w[(size_t)i * DH4]);
        const float  s = sf[i];
        acc.x += s * v.x; acc.y += s * v.y;
        acc.z += s * v.z; acc.w += s * v.w;
    }
    g_part1[blockIdx.y * DH4 + j4] = acc;
}

// ---------------------------------------------------------------------------
// Kernel 3: reduce1 + h1 compaction. 256 blocks x 256 threads.
// Block owns the 16 h1 values of gemv2 group blockIdx.x. After the tree,
// thread 0 compacts the nonzeros IN ASCENDING ORDER (accumulation order in
// gemv2 is therefore identical to the branch version) into g_cidx/g_cval.
// ---------------------------------------------------------------------------
__global__ void k_reduce1(const float4* __restrict__ b1)
{
    cudaGridDependencySynchronize();

    const int t   = threadIdx.x;
    const int jl4 = t & 3;
    const int kq  = t >> 2;                  // 0..63
    const int j4  = blockIdx.x * 4 + jl4;

    float4 a = make_float4(0.f, 0.f, 0.f, 0.f);
    #pragma unroll
    for (int k = 0; k < SPLIT1 / 64; k++) {  // 4 independent loads
        const float4 v = g_part1[(size_t)(kq * (SPLIT1 / 64) + k) * DH4 + j4];
        a.x += v.x; a.y += v.y; a.z += v.z; a.w += v.w;
    }

    __shared__ float4 sm[64][4];
    __shared__ float  hv[ROWS2];
    sm[kq][jl4] = a;
    __syncthreads();
    for (int st = 32; st >= 1; st >>= 1) {
        if (kq < st) {
            const float4 v = sm[kq + st][jl4];
            sm[kq][jl4].x += v.x; sm[kq][jl4].y += v.y;
            sm[kq][jl4].z += v.z; sm[kq][jl4].w += v.w;
        }
        __syncthreads();
    }

    if (t < 4) {
        float4 s = b1[blockIdx.x * 4 + t];
        const float4 v = sm[0][t];
        hv[t * 4 + 0] = fmaxf(s.x + v.x, 0.f);
        hv[t * 4 + 1] = fmaxf(s.y + v.y, 0.f);
        hv[t * 4 + 2] = fmaxf(s.z + v.z, 0.f);
        hv[t * 4 + 3] = fmaxf(s.w + v.w, 0.f);
    }
    __syncthreads();
    if (t == 0) {                            // 16-element compaction, once
        int n = 0;
        #pragma unroll
        for (int i = 0; i < ROWS2; i++) {
            const float s = hv[i];
            if (s != 0.0f) {
                g_cidx[blockIdx.x][n] = i;
                g_cval[blockIdx.x][n] = s;
                n++;
            }
        }
        g_nnz[blockIdx.x] = n;
    }
}

// ---------------------------------------------------------------------------
// Kernel 4: GEMV2 split-K over COMPACTED nonzero rows (branch-free, batched).
// grid (8, 256) = 2048 blocks, 128 threads. Ascending compacted order =>
// accumulation order identical to the branch version.
// ---------------------------------------------------------------------------
__global__ void k_gemv2(const float4* __restrict__ W2)
{
    cudaGridDependencySynchronize();

    const int t  = threadIdx.x;
    const int g  = blockIdx.y;               // h1 group == row block
    const int j4 = blockIdx.x * 128 + t;
    const int i0 = g * ROWS2;

    __shared__ int   sidx[ROWS2];
    __shared__ float sval[ROWS2];
    __shared__ int   snnz;
    if (t == 0) snnz = g_nnz[g];
    if (t < ROWS2) { sidx[t] = g_cidx[g][t]; sval[t] = g_cval[g][t]; }
    __syncthreads();
    const int nnz = snnz;

    float4 acc = make_float4(0.f, 0.f, 0.f, 0.f);
    const float4* __restrict__ w = W2 + (size_t)i0 * DH4 + j4;

    int i = 0;
    for (; i + 4 <= nnz; i += 4) {           // 4 loads in flight
        const float4 v0 = __ldcs(&w[(size_t)sidx[i]     * DH4]);
        const float4 v1 = __ldcs(&w[(size_t)sidx[i + 1] * DH4]);
        const float4 v2 = __ldcs(&w[(size_t)sidx[i + 2] * DH4]);
        const float4 v3 = __ldcs(&w[(size_t)sidx[i + 3] * DH4]);
        const float s0 = sval[i],     s1 = sval[i + 1];
        const float s2 = sval[i + 2], s3 = sval[i + 3];
        acc.x += s0 * v0.x; acc.y += s0 * v0.y; acc.z += s0 * v0.z; acc.w += s0 * v0.w;
        acc.x += s1 * v1.x; acc.y += s1 * v1.y; acc.z += s1 * v1.z; acc.w += s1 * v1.w;
        acc.x += s2 * v2.x; acc.y += s2 * v2.y; acc.z += s2 * v2.z; acc.w += s2 * v2.w;
        acc.x += s3 * v3.x; acc.y += s3 * v3.y; acc.z += s3 * v3.z; acc.w += s3 * v3.w;
    }
    for (; i < nnz; i++) {
        const float4 v = __ldcs(&w[(size_t)sidx[i] * DH4]);
        const float  s = sval[i];
        acc.x += s * v.x; acc.y += s * v.y;
        acc.z += s * v.z; acc.w += s * v.w;
    }
    g_part2[g * DH4 + j4] = acc;
}

// ---------------------------------------------------------------------------
// Kernel 5: fused reduce2 + heads partials. 256 blocks x 256 threads.
// ---------------------------------------------------------------------------
__global__ void k_hred(const float4* __restrict__ b2,
                       const float* __restrict__ Wloc,
                       const float* __restrict__ Wact)
{
    cudaGridDependencySynchronize();

    const int t  = threadIdx.x;
    const int j0 = blockIdx.x * 16;          // first fc7 index of this block

    __shared__ float4 sm4[64][4];
    __shared__ float  fc7s[16];

    {   // phase 1: thread (jl4 = t&3, kq = t>>2) sums 4 float4 partials
        const int jl4 = t & 3;
        const int kq  = t >> 2;
        const int j4  = blockIdx.x * 4 + jl4;
        float4 a = make_float4(0.f, 0.f, 0.f, 0.f);
        #pragma unroll
        for (int k = 0; k < SPLIT2 / 64; k++) {
            const float4 v = g_part2[(size_t)(kq * (SPLIT2 / 64) + k) * DH4 + j4];
            a.x += v.x; a.y += v.y; a.z += v.z; a.w += v.w;
        }
        sm4[kq][jl4] = a;
    }
    __syncthreads();
    {
        const int jl4 = t & 3;
        const int kq  = t >> 2;
        for (int st = 32; st >= 1; st >>= 1) {
            if (kq < st) {
                const float4 v = sm4[kq + st][jl4];
                sm4[kq][jl4].x += v.x; sm4[kq][jl4].y += v.y;
                sm4[kq][jl4].z += v.z; sm4[kq][jl4].w += v.w;
            }
            __syncthreads();
        }
    }
    if (t < 4) {
        const int j4 = blockIdx.x * 4 + t;
        float4 s = b2[j4];
        const float4 v = sm4[0][t];
        fc7s[t * 4 + 0] = fmaxf(s.x + v.x, 0.f);
        fc7s[t * 4 + 1] = fmaxf(s.y + v.y, 0.f);
        fc7s[t * 4 + 2] = fmaxf(s.z + v.z, 0.f);
        fc7s[t * 4 + 3] = fmaxf(s.w + v.w, 0.f);
    }
    __syncthreads();

    // phase 2: partial dots. thread t -> (o = t/8, q = t%8), 2 terms each.
    __shared__ float sp[31][8];
    const int o = t >> 3;
    const int q = t & 7;
    if (o < 31) {
        float p = 0.0f;
        #pragma unroll
        for (int m = 0; m < 2; m++) {
            const int idx = q * 2 + m;
            const float f = fc7s[idx];
            p += (o < 4) ? f * Wloc[(j0 + idx) * 4 + o]
                         : f * Wact[(j0 + idx) * NACT + (o - 4)];
        }
        sp[o][q] = p;
    }
    __syncthreads();
    if (o < 31 && q == 0) {
        float s = 0.0f;
        #pragma unroll
        for (int m = 0; m < 8; m++) s += sp[o][m];
        g_hp[blockIdx.x * 31 + o] = s;
    }
}

// ---------------------------------------------------------------------------
// Kernel 6: final — head partial sums (2-stage), inline box decode for all
// 20 labels, gaussian pick, output assembly. 1 block, 256 threads.
// ---------------------------------------------------------------------------
__global__ void k_final(const float* __restrict__ bloc,
                        const float* __restrict__ bact,
                        const float* __restrict__ off,
                        const float* __restrict__ rois,
                        const int*   __restrict__ imgshape,
                        float* __restrict__ out)
{
    cudaGridDependencySynchronize();

    const int t = threadIdx.x;
    const int o = t & 31;
    const int c = t >> 5;                    // 0..7
    __shared__ float sp2[8][32];
    __shared__ float locs[4];
    __shared__ float kbox[20][4];

    {   // head partial sums, stage 1
        float s = 0.0f;
        if (o < 31) {
            #pragma unroll 4
            for (int b = c * (HB / 8); b < (c + 1) * (HB / 8); b++)
                s += g_hp[b * 31 + o];
        }
        sp2[c][o] = s;
    }
    // inline selB: threads 32..51 decode the 20 label boxes
    if (t >= 32 && t < 52) {
        float box[4];
        decode_label_box(t - 32, off, rois, imgshape, box);
        kbox[t - 32][0] = box[0]; kbox[t - 32][1] = box[1];
        kbox[t - 32][2] = box[2]; kbox[t - 32][3] = box[3];
    }
    __syncthreads();
    if (t < 31) {       // head sums, stage 2
        float s = (t < 4) ? bloc[t] : bact[t - 4];
        #pragma unroll
        for (int m = 0; m < 8; m++) s += sp2[m][t];
        if (t < 4) locs[t] = s;
        else       out[8 + (t - 4)] = s;     // action scores
    }
    __syncthreads();
    if (t != 0) return;

    const float img0 = (float)imgshape[0];
    const float img1 = (float)imgshape[1];

    const float hb0 = kbox[HUMAN_LBL][0], hb1 = kbox[HUMAN_LBL][1];
    const float hb2 = kbox[HUMAN_LBL][2], hb3 = kbox[HUMAN_LBL][3];
    const float hw_ = hb3 - hb1, hh_ = hb2 - hb0;
    const float h4x = 0.5f * hw_, h4y = 0.5f * hh_;
    const float hw = fmaxf(hw_, 1e-3f), hh = fmaxf(hh_, 1e-3f);

    const float mw = locs[3] - locs[1], mh = locs[2] - locs[0];
    const float mu0 = 0.5f * mw, mu1 = 0.5f * mh, mu2 = mw, mu3 = mh;

    float best = -1.0f;
    int   bl   = 0;
    for (int l = 0; l < 20; l++) {
        if (l == HUMAN_LBL) continue;
        const float b0 = kbox[l][0], b1 = kbox[l][1];
        const float b2 = kbox[l][2], b3 = kbox[l][3];
        const float cw_ = b3 - b1, ch_ = b2 - b0;
        const float cx = 0.5f * cw_, cy = 0.5f * ch_;
        const float cw = fmaxf(cw_, 1e-3f), ch = fmaxf(ch_, 1e-3f);
        const float d0 = (cx - h4x) / hw - mu0;
        const float d1 = (cy - h4y) / hh - mu1;
        const float d2 = logf(cw / hw) - mu2;
        const float d3 = logf(ch / hh) - mu3;
        const float gau = expf(-(d0*d0 + d1*d1 + d2*d2 + d3*d3) /
                               (2.0f * 0.3f * 0.3f));
        if (gau > best) { best = gau; bl = l; }
    }

    const float invy = img0 / (float)HFE;
    const float invx = img1 / (float)WFE;
    out[0] = hb0 * invy; out[1] = hb1 * invx;
    out[2] = hb2 * invy; out[3] = hb3 * invx;
    out[4] = kbox[bl][0] * invy; out[5] = kbox[bl][1] * invx;
    out[6] = kbox[bl][2] * invy; out[7] = kbox[bl][3] * invx;
    out[35] = (float)HFE / img0;
}

// ---------------------------------------------------------------------------
// PDL launch helper
// ---------------------------------------------------------------------------
static void launch_pdl(const void* func, dim3 grid, dim3 block, void** args)
{
    cudaLaunchConfig_t cfg = {};
    cfg.gridDim  = grid;
    cfg.blockDim = block;
    cudaLaunchAttribute attr[1];
    attr[0].id = cudaLaunchAttributeProgrammaticStreamSerialization;
    attr[0].val.programmaticStreamSerializationAllowed = 1;
    cfg.attrs = attr;
    cfg.numAttrs = 1;
    cudaLaunchKernelExC(&cfg, func, args);
}

// ---------------------------------------------------------------------------
extern "C" void kernel_launch(void* const* d_in, const int* in_sizes, int n_in,
                              void* d_out, int out_size)
{
    const float* x        = (const float*)d_in[0];
    const float* pscores  = (const float*)d_in[1];
    const float* poff     = (const float*)d_in[2];
    const float* rois     = (const float*)d_in[3];
    const int*   imgshape = (const int*)  d_in[4];
    const float* W1f      = (const float*)d_in[5];
    const float* b1f      = (const float*)d_in[6];
    const float* W2f      = (const float*)d_in[7];
    const float* b2f      = (const float*)d_in[8];
    const float* Wloc     = (const float*)d_in[9];
    const float* bloc     = (const float*)d_in[10];
    const float* Wact     = (const float*)d_in[11];
    const float* bact     = (const float*)d_in[12];
    float* out = (float*)d_out;
    const float4* W1 = (const float4*)W1f;
    const float4* W2 = (const float4*)W2f;
    const float4* b1 = (const float4*)b1f;
    const float4* b2 = (const float4*)b2f;

    {   void* a[] = {(void*)&pscores, (void*)&Wloc, (void*)&Wact};
        launch_pdl((const void*)k_selA, dim3(SELC, 21), dim3(256), a); }
    {   void* a[] = {(void*)&W1, (void*)&x, (void*)&poff, (void*)&rois,
                     (void*)&imgshape};
        launch_pdl((const void*)k_gemv1, dim3(8, SPLIT1), dim3(128), a); }
    {   void* a[] = {(void*)&b1};
        launch_pdl((const void*)k_reduce1, dim3(256), dim3(256), a); }
    {   void* a[] = {(void*)&W2};
        launch_pdl((const void*)k_gemv2, dim3(8, SPLIT2), dim3(128), a); }
    {   void* a[] = {(void*)&b2, (void*)&Wloc, (void*)&Wact};
        launch_pdl((const void*)k_hred, dim3(HB), dim3(256), a); }
    {   void* a[] = {(void*)&bloc, (void*)&bact, (void*)&poff, (void*)&rois,
                     (void*)&imgshape, (void*)&out};
        launch_pdl((const void*)k_final, dim3(1), dim3(256), a); }
}